// round 8
// baseline (speedup 1.0000x reference)
#include <cuda_runtime.h>
#include <cuda_bf16.h>
#include <stdint.h>

// Problem constants
#define B_   128
#define L_   100
#define F_   900
#define D_   512
#define E_   8

#define BN   128
#define BK   32      // 32 fp32 per k-tile row
#define NKT  29      // ceil(900/32), padded to 928
#define FP   928     // padded F for x split arrays
#define NROWS (B_ * L_)   // 12800

// Shared memory layout (dynamic)
#define SM_BM     0
#define SM_STAGES 1024
#define STAGE_BYTES 32768
#define OFF_A_HI  0
#define OFF_A_LO  8192
#define OFF_B_HI  16384
#define OFF_B_LO  24576
#define SM_RAW    (SM_STAGES + 2 * STAGE_BYTES)   // 66560
#define RAW_BYTES 32768                            // 8 chunks x 256 thr x 16B
#define SMEM_TOTAL (SM_RAW + RAW_BYTES)            // 99328 -> 2 CTAs/SM

// Global scratch
__device__ __nv_bfloat16 g_xhi[(size_t)NROWS * FP];
__device__ __nv_bfloat16 g_xlo[(size_t)NROWS * FP];
__device__ int2   g_topk_idx[B_];
__device__ float2 g_topk_w[B_];

// ---------------- helpers ----------------
__device__ __forceinline__ uint32_t smem_u32(const void* p) {
    uint32_t a;
    asm("{ .reg .u64 t; cvta.to.shared.u64 t, %1; cvt.u32.u64 %0, t; }" : "=r"(a) : "l"(p));
    return a;
}
// 64B rows: phys quarter = q ^ ((row>>1)&3) -> ldmatrix conflict-free
__device__ __forceinline__ uint32_t swoff(int row, int q) {
    return (uint32_t)(row * 64) + (uint32_t)((q ^ ((row >> 1) & 3)) << 4);
}
__device__ __forceinline__ void cp16(uint32_t dst, const void* src, uint32_t sz) {
    asm volatile("cp.async.cg.shared.global [%0], [%1], 16, %2;"
                 :: "r"(dst), "l"(src), "r"(sz) : "memory");
}
#define CP_COMMIT() asm volatile("cp.async.commit_group;" ::: "memory")
#define CP_WAIT0()  asm volatile("cp.async.wait_group 0;" ::: "memory")

#define LDSM4(r, addr) \
    asm volatile("ldmatrix.sync.aligned.m8n8.x4.shared.b16 {%0,%1,%2,%3}, [%4];" \
        : "=r"((r)[0]), "=r"((r)[1]), "=r"((r)[2]), "=r"((r)[3]) : "r"(addr))
#define LDSM2(r, addr) \
    asm volatile("ldmatrix.sync.aligned.m8n8.x2.shared.b16 {%0,%1}, [%2];" \
        : "=r"((r)[0]), "=r"((r)[1]) : "r"(addr))
#define MMA16816(c, a, bb) \
    asm volatile("mma.sync.aligned.m16n8k16.row.col.f32.bf16.bf16.f32 " \
        "{%0,%1,%2,%3}, {%4,%5,%6,%7}, {%8,%9}, {%0,%1,%2,%3};" \
        : "+f"((c)[0]), "+f"((c)[1]), "+f"((c)[2]), "+f"((c)[3]) \
        : "r"((a)[0]), "r"((a)[1]), "r"((a)[2]), "r"((a)[3]), "r"((bb)[0]), "r"((bb)[1]))

// ---------------------------------------------------------------------------
// Kernel 0: split x into bf16 hi/lo, zero-padded cols to FP=928
// ---------------------------------------------------------------------------
__global__ void split_x_kernel(const float* __restrict__ x) {
    int idx = blockIdx.x * 256 + threadIdx.x;     // one per 8 cols
    if (idx >= NROWS * (FP / 8)) return;
    int row = idx / (FP / 8);
    int c8  = idx % (FP / 8);
    int f   = c8 * 8;
    const float* xr = x + (size_t)row * F_ + f;
    uint32_t hi[4], lo[4];
#pragma unroll
    for (int j = 0; j < 4; j++) {
        float v0 = (f + 2 * j     < F_) ? xr[2 * j]     : 0.f;
        float v1 = (f + 2 * j + 1 < F_) ? xr[2 * j + 1] : 0.f;
        __nv_bfloat16 h0 = __float2bfloat16_rn(v0);
        __nv_bfloat16 h1 = __float2bfloat16_rn(v1);
        __nv_bfloat162 hp; hp.x = h0; hp.y = h1;
        __nv_bfloat162 lp; lp.x = __float2bfloat16_rn(v0 - __bfloat162float(h0));
                           lp.y = __float2bfloat16_rn(v1 - __bfloat162float(h1));
        hi[j] = *(uint32_t*)&hp;
        lo[j] = *(uint32_t*)&lp;
    }
    *(uint4*)(g_xhi + (size_t)row * FP + f) = make_uint4(hi[0], hi[1], hi[2], hi[3]);
    *(uint4*)(g_xlo + (size_t)row * FP + f) = make_uint4(lo[0], lo[1], lo[2], lo[3]);
}

// ---------------------------------------------------------------------------
// Kernel 1: gates (self-disambiguates logits vs masks by bit pattern)
// ---------------------------------------------------------------------------
__global__ void gates_kernel(const void* __restrict__ candA,
                             const void* __restrict__ candB) {
    int b = threadIdx.x;
    if (b >= B_) return;
    const int* ai = (const int*)candA;
    bool aIsMask = true;
#pragma unroll
    for (int e = 0; e < E_; e++) {
        int t = ai[b * E_ + e];
        if (t != 0 && t != 1) aIsMask = false;
    }
    const float* logits = aIsMask ? (const float*)candB : (const float*)candA;
    const int*   masks  = aIsMask ? (const int*)candA   : (const int*)candB;

    float v[E_]; float mx = -1e30f;
#pragma unroll
    for (int e = 0; e < E_; e++) { v[e] = logits[b * E_ + e]; mx = fmaxf(mx, v[e]); }
    float s = 0.f;
#pragma unroll
    for (int e = 0; e < E_; e++) { v[e] = expf(v[e] - mx); s += v[e]; }
    float inv = 1.f / s;
#pragma unroll
    for (int e = 0; e < E_; e++) {
        float m = (masks[b * E_ + e] == 1) ? 1.f : 0.f;
        v[e] = v[e] * inv * m;
    }
    int i1 = 0;
#pragma unroll
    for (int e = 1; e < E_; e++) if (v[e] > v[i1]) i1 = e;
    int i2 = (i1 == 0) ? 1 : 0;
#pragma unroll
    for (int e = 0; e < E_; e++) if (e != i1 && v[e] > v[i2]) i2 = e;
    float g1 = v[i1], g2 = v[i2];
    float invs = 1.f / (g1 + g2 + 1e-9f);
    g_topk_idx[b] = make_int2(i1, i2);
    g_topk_w[b]   = make_float2(g1 * invs, g2 * invs);
}

// ---------------------------------------------------------------------------
// Stage issue: cp.async A split tiles (final form) + raw W1/W2 chunks.
// Each thread stages exactly the raw chunks it will transform.
// ---------------------------------------------------------------------------
__device__ __forceinline__ void issue_stage(
    uint32_t stage_u, uint32_t raw_u,
    const __nv_bfloat16* __restrict__ xhi_b, const __nv_bfloat16* __restrict__ xlo_b,
    const float* __restrict__ W1, const float* __restrict__ W2,
    int k0, int tid) {
    // A: 2 items (row, q) -> 16B hi + 16B lo each
#pragma unroll
    for (int it = 0; it < 2; it++) {
        int i   = tid + it * 256;
        int row = i >> 2, q = i & 3;
        int rc  = (row < L_) ? row : 0;
        uint32_t sz = (row < L_) ? 16u : 0u;
        const __nv_bfloat16* sh = xhi_b + (size_t)rc * FP + k0 + q * 8;
        const __nv_bfloat16* sl = xlo_b + (size_t)rc * FP + k0 + q * 8;
        uint32_t off = swoff(row, q);
        cp16(stage_u + OFF_A_HI + off, sh, sz);
        cp16(stage_u + OFF_A_LO + off, sl, sz);
    }
    // W raw: 2 items x 4 chunks (W1 f0, W1 f0+4, W2 f0, W2 f0+4)
#pragma unroll
    for (int it = 0; it < 2; it++) {
        int i   = tid + it * 256;
        int row = i >> 2, q = i & 3;
        int f0  = k0 + q * 8;
        const float* w1p = W1 + (size_t)row * F_ + f0;
        const float* w2p = W2 + (size_t)row * F_ + f0;
        uint32_t d  = raw_u + it * 16384 + tid * 16;
        uint32_t s0 = (f0 < F_)     ? 16u : 0u;
        uint32_t s1 = (f0 + 4 < F_) ? 16u : 0u;
        cp16(d,         (f0 < F_)     ? w1p     : W1, s0);
        cp16(d + 4096,  (f0 + 4 < F_) ? w1p + 4 : W1, s1);
        cp16(d + 8192,  (f0 < F_)     ? w2p     : W2, s0);
        cp16(d + 12288, (f0 + 4 < F_) ? w2p + 4 : W2, s1);
    }
}

// Transform: read own raw chunks (LDS), mix in fp32, split to bf16 hi/lo, STS.
__device__ __forceinline__ void transform_stage(
    char* __restrict__ smem, int stage, float gx, float gy, int tid) {
    char* stg = smem + SM_STAGES + stage * STAGE_BYTES;
#pragma unroll
    for (int it = 0; it < 2; it++) {
        int i   = tid + it * 256;
        int row = i >> 2, q = i & 3;
        const char* rb = smem + SM_RAW + it * 16384 + tid * 16;
        float4 a0 = *(const float4*)(rb);
        float4 a1 = *(const float4*)(rb + 4096);
        float4 c0 = *(const float4*)(rb + 8192);
        float4 c1 = *(const float4*)(rb + 12288);
        float v[8];
        v[0] = fmaf(gx, a0.x, gy * c0.x); v[1] = fmaf(gx, a0.y, gy * c0.y);
        v[2] = fmaf(gx, a0.z, gy * c0.z); v[3] = fmaf(gx, a0.w, gy * c0.w);
        v[4] = fmaf(gx, a1.x, gy * c1.x); v[5] = fmaf(gx, a1.y, gy * c1.y);
        v[6] = fmaf(gx, a1.z, gy * c1.z); v[7] = fmaf(gx, a1.w, gy * c1.w);
        uint32_t hi[4], lo[4];
#pragma unroll
        for (int j = 0; j < 4; j++) {
            __nv_bfloat16 h0 = __float2bfloat16_rn(v[2 * j]);
            __nv_bfloat16 h1 = __float2bfloat16_rn(v[2 * j + 1]);
            __nv_bfloat162 hp; hp.x = h0; hp.y = h1;
            __nv_bfloat162 lp;
            lp.x = __float2bfloat16_rn(v[2 * j]     - __bfloat162float(h0));
            lp.y = __float2bfloat16_rn(v[2 * j + 1] - __bfloat162float(h1));
            hi[j] = *(uint32_t*)&hp;
            lo[j] = *(uint32_t*)&lp;
        }
        uint32_t off = swoff(row, q);
        *(uint4*)(stg + OFF_B_HI + off) = make_uint4(hi[0], hi[1], hi[2], hi[3]);
        *(uint4*)(stg + OFF_B_LO + off) = make_uint4(lo[0], lo[1], lo[2], lo[3]);
    }
}

// ---------------------------------------------------------------------------
// Kernel 2: HMMA bf16 3-pass split GEMM, cp.async pipelined producer.
// ---------------------------------------------------------------------------
__global__ void __launch_bounds__(256, 2)
moe_hmma_kernel(const float* __restrict__ W,
                const float* __restrict__ bias,
                float* __restrict__ out) {
    extern __shared__ char smem[];
    const uint32_t sb = smem_u32(smem);
    float* bm = (float*)(smem + SM_BM);

    const int tid    = threadIdx.x;
    const int wid    = tid >> 5;
    const int lane   = tid & 31;
    const int warp_m = wid >> 2;
    const int warp_n = wid & 3;
    const int b      = blockIdx.y;
    const int dtile  = blockIdx.x;

    const int2   ei = g_topk_idx[b];
    const float2 gw = g_topk_w[b];

    const __nv_bfloat16* xhi_b = g_xhi + (size_t)b * L_ * FP;
    const __nv_bfloat16* xlo_b = g_xlo + (size_t)b * L_ * FP;
    const float* __restrict__ W1 = W + (size_t)ei.x * D_ * F_ + (size_t)dtile * BN * F_;
    const float* __restrict__ W2 = W + (size_t)ei.y * D_ * F_ + (size_t)dtile * BN * F_;

    if (tid < BN) {
        int d = dtile * BN + tid;
        bm[tid] = gw.x * bias[ei.x * D_ + d] + gw.y * bias[ei.y * D_ + d];
    }

    float acc[4][4][4];
#pragma unroll
    for (int mi = 0; mi < 4; mi++)
#pragma unroll
        for (int nj = 0; nj < 4; nj++)
#pragma unroll
            for (int q = 0; q < 4; q++) acc[mi][nj][q] = 0.f;

    const uint32_t raw_u = sb + SM_RAW;

    // prologue: stage 0
    issue_stage(sb + SM_STAGES, raw_u, xhi_b, xlo_b, W1, W2, 0, tid);
    CP_COMMIT();
    CP_WAIT0();
    transform_stage(smem, 0, gw.x, gw.y, tid);
    __syncthreads();

    const int arow0 = warp_m * 64 + (lane & 15);
    const int ahalf = lane >> 4;
    const int brow0 = warp_n * 32 + (lane & 7);
    const int bhalf = (lane >> 3) & 1;

    for (int t = 0; t < NKT; t++) {
        // issue loads for t+1 BEFORE consuming t (latency hides behind MMA)
        if (t + 1 < NKT) {
            issue_stage(sb + SM_STAGES + ((t + 1) & 1) * STAGE_BYTES, raw_u,
                        xhi_b, xlo_b, W1, W2, (t + 1) * BK, tid);
            CP_COMMIT();
        }

        const uint32_t aHiB = sb + SM_STAGES + (t & 1) * STAGE_BYTES + OFF_A_HI;
        const uint32_t aLoB = aHiB + (OFF_A_LO - OFF_A_HI);
        const uint32_t bHiB = aHiB + (OFF_B_HI - OFF_A_HI);
        const uint32_t bLoB = aHiB + (OFF_B_LO - OFF_A_HI);

#pragma unroll
        for (int s = 0; s < 2; s++) {
            const int aq = 2 * s + ahalf;
            const int bq = 2 * s + bhalf;
            uint32_t aX[4][4];

            // pass A-hi: hi*hi + hi*lo
#pragma unroll
            for (int mi = 0; mi < 4; mi++)
                LDSM4(aX[mi], aHiB + swoff(arow0 + mi * 16, aq));
#pragma unroll
            for (int nj = 0; nj < 4; nj++) {
                uint32_t bh[2], bl[2];
                uint32_t boff = swoff(brow0 + nj * 8, bq);
                LDSM2(bh, bHiB + boff);
                LDSM2(bl, bLoB + boff);
#pragma unroll
                for (int mi = 0; mi < 4; mi++) {
                    MMA16816(acc[mi][nj], aX[mi], bh);
                    MMA16816(acc[mi][nj], aX[mi], bl);
                }
            }
            // pass A-lo: lo*hi
#pragma unroll
            for (int mi = 0; mi < 4; mi++)
                LDSM4(aX[mi], aLoB + swoff(arow0 + mi * 16, aq));
#pragma unroll
            for (int nj = 0; nj < 4; nj++) {
                uint32_t bh[2];
                LDSM2(bh, bHiB + swoff(brow0 + nj * 8, bq));
#pragma unroll
                for (int mi = 0; mi < 4; mi++)
                    MMA16816(acc[mi][nj], aX[mi], bh);
            }
        }

        if (t + 1 < NKT) {
            CP_WAIT0();   // own chunks landed (A in final form; W raw private)
            transform_stage(smem, (t + 1) & 1, gw.x, gw.y, tid);
        }
        __syncthreads();
    }

    // ---- epilogue ----
    const int r_base = warp_m * 64 + (lane >> 2);
    const int c_base = warp_n * 32 + ((lane & 3) << 1);
#pragma unroll
    for (int mi = 0; mi < 4; mi++) {
#pragma unroll
        for (int half = 0; half < 2; half++) {
            int l = r_base + mi * 16 + half * 8;
            if (l >= L_) continue;
            float* orow = out + ((size_t)b * L_ + l) * D_ + dtile * BN;
#pragma unroll
            for (int nj = 0; nj < 4; nj++) {
                int c = c_base + nj * 8;
                float v0 = acc[mi][nj][half * 2 + 0] + bm[c];
                float v1 = acc[mi][nj][half * 2 + 1] + bm[c + 1];
                v0 = __bfloat162float(__float2bfloat16_rn(v0));
                v1 = __bfloat162float(__float2bfloat16_rn(v1));
                *(float2*)(orow + c) = make_float2(v0, v1);
            }
        }
    }
}

// ---------------------------------------------------------------------------
extern "C" void kernel_launch(void* const* d_in, const int* in_sizes, int n_in,
                              void* d_out, int out_size) {
    const void* x_p = nullptr;
    const void* W_p = nullptr;
    const void* b_p = nullptr;
    const void* c1024[2] = {nullptr, nullptr};
    int n1024 = 0;

    for (int i = 0; i < n_in; i++) {
        switch (in_sizes[i]) {
            case 11520000: x_p = d_in[i]; break;
            case 3686400:  W_p = d_in[i]; break;
            case 4096:     b_p = d_in[i]; break;
            case 1024: if (n1024 < 2) c1024[n1024++] = d_in[i]; break;
            default: break;
        }
    }
    if (!x_p || !W_p || !b_p || n1024 != 2) {
        x_p = d_in[0]; c1024[0] = d_in[1]; c1024[1] = d_in[2];
        W_p = d_in[3]; b_p = d_in[4];
    }

    float* out = (float*)d_out;

    cudaFuncSetAttribute(moe_hmma_kernel,
                         cudaFuncAttributeMaxDynamicSharedMemorySize, SMEM_TOTAL);

    gates_kernel<<<1, B_>>>(c1024[0], c1024[1]);
    split_x_kernel<<<(NROWS * (FP / 8) + 255) / 256, 256>>>((const float*)x_p);

    dim3 grid(D_ / BN, B_);   // (4, 128)
    moe_hmma_kernel<<<grid, 256, SMEM_TOTAL>>>((const float*)W_p,
                                               (const float*)b_p, out);
}

// round 9
// speedup vs baseline: 1.4455x; 1.4455x over previous
#include <cuda_runtime.h>
#include <cuda_bf16.h>
#include <stdint.h>

// Problem constants
#define B_   128
#define L_   100
#define F_   900
#define D_   512
#define E_   8

#define BN   128
#define BK   32      // 32 cols per k-tile
#define NKT  29      // ceil(900/32), padded to 928
#define FP   928
#define NROWS (B_ * L_)

// Shared memory layout (dynamic)
#define SM_BM     0
#define SM_STAGES 1024
#define STAGE_BYTES 32768
#define OFF_A_HI  0
#define OFF_A_LO  8192
#define OFF_B_HI  16384
#define OFF_B_LO  24576
#define SMEM_TOTAL (SM_STAGES + 2 * STAGE_BYTES)   // 66560 -> 2 CTAs/SM

// Global scratch
__device__ __nv_bfloat16 g_xhi[(size_t)NROWS * FP];
__device__ __nv_bfloat16 g_xlo[(size_t)NROWS * FP];
__device__ int2   g_topk_idx[B_];
__device__ float2 g_topk_w[B_];

// ---------------- helpers ----------------
__device__ __forceinline__ uint32_t smem_u32(const void* p) {
    uint32_t a;
    asm("{ .reg .u64 t; cvta.to.shared.u64 t, %1; cvt.u32.u64 %0, t; }" : "=r"(a) : "l"(p));
    return a;
}
// 64B rows: phys quarter = q ^ ((row>>1)&3) -> ldmatrix conflict-free
__device__ __forceinline__ uint32_t swoff(int row, int q) {
    return (uint32_t)(row * 64) + (uint32_t)((q ^ ((row >> 1) & 3)) << 4);
}
__device__ __forceinline__ void cp16(uint32_t dst, const void* src, uint32_t sz) {
    asm volatile("cp.async.cg.shared.global [%0], [%1], 16, %2;"
                 :: "r"(dst), "l"(src), "r"(sz) : "memory");
}
#define CP_COMMIT() asm volatile("cp.async.commit_group;" ::: "memory")
#define CP_WAIT0()  asm volatile("cp.async.wait_group 0;" ::: "memory")

#define LDSM4(r, addr) \
    asm volatile("ldmatrix.sync.aligned.m8n8.x4.shared.b16 {%0,%1,%2,%3}, [%4];" \
        : "=r"((r)[0]), "=r"((r)[1]), "=r"((r)[2]), "=r"((r)[3]) : "r"(addr))
#define LDSM2(r, addr) \
    asm volatile("ldmatrix.sync.aligned.m8n8.x2.shared.b16 {%0,%1}, [%2];" \
        : "=r"((r)[0]), "=r"((r)[1]) : "r"(addr))
#define MMA16816(c, a, bb) \
    asm volatile("mma.sync.aligned.m16n8k16.row.col.f32.bf16.bf16.f32 " \
        "{%0,%1,%2,%3}, {%4,%5,%6,%7}, {%8,%9}, {%0,%1,%2,%3};" \
        : "+f"((c)[0]), "+f"((c)[1]), "+f"((c)[2]), "+f"((c)[3]) \
        : "r"((a)[0]), "r"((a)[1]), "r"((a)[2]), "r"((a)[3]), "r"((bb)[0]), "r"((bb)[1]))

// ---------------------------------------------------------------------------
// Kernel 0: split x into bf16 hi/lo, zero-padded cols to FP=928
// ---------------------------------------------------------------------------
__global__ void split_x_kernel(const float* __restrict__ x) {
    int idx = blockIdx.x * 256 + threadIdx.x;
    if (idx >= NROWS * (FP / 8)) return;
    int row = idx / (FP / 8);
    int c8  = idx % (FP / 8);
    int f   = c8 * 8;
    const float* xr = x + (size_t)row * F_ + f;
    uint32_t hi[4], lo[4];
#pragma unroll
    for (int j = 0; j < 4; j++) {
        float v0 = (f + 2 * j     < F_) ? xr[2 * j]     : 0.f;
        float v1 = (f + 2 * j + 1 < F_) ? xr[2 * j + 1] : 0.f;
        __nv_bfloat16 h0 = __float2bfloat16_rn(v0);
        __nv_bfloat16 h1 = __float2bfloat16_rn(v1);
        __nv_bfloat162 hp; hp.x = h0; hp.y = h1;
        __nv_bfloat162 lp; lp.x = __float2bfloat16_rn(v0 - __bfloat162float(h0));
                           lp.y = __float2bfloat16_rn(v1 - __bfloat162float(h1));
        hi[j] = *(uint32_t*)&hp;
        lo[j] = *(uint32_t*)&lp;
    }
    *(uint4*)(g_xhi + (size_t)row * FP + f) = make_uint4(hi[0], hi[1], hi[2], hi[3]);
    *(uint4*)(g_xlo + (size_t)row * FP + f) = make_uint4(lo[0], lo[1], lo[2], lo[3]);
}

// ---------------------------------------------------------------------------
// Kernel 1: gates (self-disambiguates logits vs masks by bit pattern)
// ---------------------------------------------------------------------------
__global__ void gates_kernel(const void* __restrict__ candA,
                             const void* __restrict__ candB) {
    int b = threadIdx.x;
    if (b >= B_) return;
    const int* ai = (const int*)candA;
    bool aIsMask = true;
#pragma unroll
    for (int e = 0; e < E_; e++) {
        int t = ai[b * E_ + e];
        if (t != 0 && t != 1) aIsMask = false;
    }
    const float* logits = aIsMask ? (const float*)candB : (const float*)candA;
    const int*   masks  = aIsMask ? (const int*)candA   : (const int*)candB;

    float v[E_]; float mx = -1e30f;
#pragma unroll
    for (int e = 0; e < E_; e++) { v[e] = logits[b * E_ + e]; mx = fmaxf(mx, v[e]); }
    float s = 0.f;
#pragma unroll
    for (int e = 0; e < E_; e++) { v[e] = expf(v[e] - mx); s += v[e]; }
    float inv = 1.f / s;
#pragma unroll
    for (int e = 0; e < E_; e++) {
        float m = (masks[b * E_ + e] == 1) ? 1.f : 0.f;
        v[e] = v[e] * inv * m;
    }
    int i1 = 0;
#pragma unroll
    for (int e = 1; e < E_; e++) if (v[e] > v[i1]) i1 = e;
    int i2 = (i1 == 0) ? 1 : 0;
#pragma unroll
    for (int e = 0; e < E_; e++) if (e != i1 && v[e] > v[i2]) i2 = e;
    float g1 = v[i1], g2 = v[i2];
    float invs = 1.f / (g1 + g2 + 1e-9f);
    g_topk_idx[b] = make_int2(i1, i2);
    g_topk_w[b]   = make_float2(g1 * invs, g2 * invs);
}

// ---------------------------------------------------------------------------
// A producer: 4 cp.async (final-form bf16 hi/lo), zero-fill pad rows.
// ---------------------------------------------------------------------------
__device__ __forceinline__ void issue_A(
    uint32_t stage_u,
    const __nv_bfloat16* __restrict__ xhi_b, const __nv_bfloat16* __restrict__ xlo_b,
    int k0, int tid) {
#pragma unroll
    for (int it = 0; it < 2; it++) {
        int i   = tid + it * 256;
        int row = i >> 2, q = i & 3;
        int rc  = (row < L_) ? row : 0;
        uint32_t sz = (row < L_) ? 16u : 0u;
        const __nv_bfloat16* sh = xhi_b + (size_t)rc * FP + k0 + q * 8;
        const __nv_bfloat16* sl = xlo_b + (size_t)rc * FP + k0 + q * 8;
        uint32_t off = swoff(row, q);
        cp16(stage_u + OFF_A_HI + off, sh, sz);
        cp16(stage_u + OFF_A_LO + off, sl, sz);
    }
}

// ---------------------------------------------------------------------------
// W producer (round-6 style): direct LDG fp32, gate-mix, split, STS.
// ---------------------------------------------------------------------------
__device__ __forceinline__ void produce_W(
    char* __restrict__ stg,
    const float* __restrict__ W1, const float* __restrict__ W2,
    float gx, float gy, int k0, int tid) {
#pragma unroll
    for (int it = 0; it < 2; it++) {
        int item = tid + it * 256;
        int row  = item >> 2;
        int q    = item & 3;
        int f    = k0 + q * 8;
        float v[8] = {0.f, 0.f, 0.f, 0.f, 0.f, 0.f, 0.f, 0.f};
        if (f + 4 <= F_) {
            float4 a = *(const float4*)(W1 + (size_t)row * F_ + f);
            float4 c = *(const float4*)(W2 + (size_t)row * F_ + f);
            v[0] = fmaf(gx, a.x, gy * c.x); v[1] = fmaf(gx, a.y, gy * c.y);
            v[2] = fmaf(gx, a.z, gy * c.z); v[3] = fmaf(gx, a.w, gy * c.w);
        }
        if (f + 8 <= F_) {
            float4 a = *(const float4*)(W1 + (size_t)row * F_ + f + 4);
            float4 c = *(const float4*)(W2 + (size_t)row * F_ + f + 4);
            v[4] = fmaf(gx, a.x, gy * c.x); v[5] = fmaf(gx, a.y, gy * c.y);
            v[6] = fmaf(gx, a.z, gy * c.z); v[7] = fmaf(gx, a.w, gy * c.w);
        }
        uint32_t hi[4], lo[4];
#pragma unroll
        for (int j = 0; j < 4; j++) {
            __nv_bfloat16 h0 = __float2bfloat16_rn(v[2 * j]);
            __nv_bfloat16 h1 = __float2bfloat16_rn(v[2 * j + 1]);
            __nv_bfloat162 hp; hp.x = h0; hp.y = h1;
            __nv_bfloat162 lp;
            lp.x = __float2bfloat16_rn(v[2 * j]     - __bfloat162float(h0));
            lp.y = __float2bfloat16_rn(v[2 * j + 1] - __bfloat162float(h1));
            hi[j] = *(uint32_t*)&hp;
            lo[j] = *(uint32_t*)&lp;
        }
        uint32_t off = swoff(row, q);
        *(uint4*)(stg + OFF_B_HI + off) = make_uint4(hi[0], hi[1], hi[2], hi[3]);
        *(uint4*)(stg + OFF_B_LO + off) = make_uint4(lo[0], lo[1], lo[2], lo[3]);
    }
}

// ---------------------------------------------------------------------------
// Kernel 2: HMMA bf16 3-pass split GEMM.
//   A prefetched via cp.async (no transform); W direct-LDG mixed/split.
// ---------------------------------------------------------------------------
__global__ void __launch_bounds__(256, 2)
moe_hmma_kernel(const float* __restrict__ W,
                const float* __restrict__ bias,
                float* __restrict__ out) {
    extern __shared__ char smem[];
    const uint32_t sb = smem_u32(smem);
    float* bm = (float*)(smem + SM_BM);

    const int tid    = threadIdx.x;
    const int wid    = tid >> 5;
    const int lane   = tid & 31;
    const int warp_m = wid >> 2;
    const int warp_n = wid & 3;
    const int b      = blockIdx.y;
    const int dtile  = blockIdx.x;

    const int2   ei = g_topk_idx[b];
    const float2 gw = g_topk_w[b];

    const __nv_bfloat16* xhi_b = g_xhi + (size_t)b * L_ * FP;
    const __nv_bfloat16* xlo_b = g_xlo + (size_t)b * L_ * FP;
    const float* __restrict__ W1 = W + (size_t)ei.x * D_ * F_ + (size_t)dtile * BN * F_;
    const float* __restrict__ W2 = W + (size_t)ei.y * D_ * F_ + (size_t)dtile * BN * F_;

    if (tid < BN) {
        int d = dtile * BN + tid;
        bm[tid] = gw.x * bias[ei.x * D_ + d] + gw.y * bias[ei.y * D_ + d];
    }

    float acc[4][4][4];
#pragma unroll
    for (int mi = 0; mi < 4; mi++)
#pragma unroll
        for (int nj = 0; nj < 4; nj++)
#pragma unroll
            for (int q = 0; q < 4; q++) acc[mi][nj][q] = 0.f;

    // prologue: stage 0
    issue_A(sb + SM_STAGES, xhi_b, xlo_b, 0, tid);
    CP_COMMIT();
    produce_W(smem + SM_STAGES, W1, W2, gw.x, gw.y, 0, tid);
    CP_WAIT0();
    __syncthreads();

    const int arow0 = warp_m * 64 + (lane & 15);
    const int ahalf = lane >> 4;
    const int brow0 = warp_n * 32 + (lane & 7);
    const int bhalf = (lane >> 3) & 1;

    for (int t = 0; t < NKT; t++) {
        // prefetch A for t+1 now; its latency hides behind this tile's MMAs
        if (t + 1 < NKT) {
            issue_A(sb + SM_STAGES + ((t + 1) & 1) * STAGE_BYTES,
                    xhi_b, xlo_b, (t + 1) * BK, tid);
            CP_COMMIT();
        }

        const uint32_t aHiB = sb + SM_STAGES + (t & 1) * STAGE_BYTES + OFF_A_HI;
        const uint32_t aLoB = aHiB + (OFF_A_LO - OFF_A_HI);
        const uint32_t bHiB = aHiB + (OFF_B_HI - OFF_A_HI);
        const uint32_t bLoB = aHiB + (OFF_B_LO - OFF_A_HI);

#pragma unroll
        for (int s = 0; s < 2; s++) {
            const int aq = 2 * s + ahalf;
            const int bq = 2 * s + bhalf;
            uint32_t aX[4][4];

            // pass A-hi: hi*hi + hi*lo
#pragma unroll
            for (int mi = 0; mi < 4; mi++)
                LDSM4(aX[mi], aHiB + swoff(arow0 + mi * 16, aq));
#pragma unroll
            for (int nj = 0; nj < 4; nj++) {
                uint32_t bh[2], bl[2];
                uint32_t boff = swoff(brow0 + nj * 8, bq);
                LDSM2(bh, bHiB + boff);
                LDSM2(bl, bLoB + boff);
#pragma unroll
                for (int mi = 0; mi < 4; mi++) {
                    MMA16816(acc[mi][nj], aX[mi], bh);
                    MMA16816(acc[mi][nj], aX[mi], bl);
                }
            }
            // pass A-lo: lo*hi
#pragma unroll
            for (int mi = 0; mi < 4; mi++)
                LDSM4(aX[mi], aLoB + swoff(arow0 + mi * 16, aq));
#pragma unroll
            for (int nj = 0; nj < 4; nj++) {
                uint32_t bh[2];
                LDSM2(bh, bHiB + swoff(brow0 + nj * 8, bq));
#pragma unroll
                for (int mi = 0; mi < 4; mi++)
                    MMA16816(acc[mi][nj], aX[mi], bh);
            }
        }

        if (t + 1 < NKT) {
            produce_W(smem + SM_STAGES + ((t + 1) & 1) * STAGE_BYTES,
                      W1, W2, gw.x, gw.y, (t + 1) * BK, tid);
            CP_WAIT0();   // A for t+1 landed (issued before the MMA section)
        }
        __syncthreads();
    }

    // ---- epilogue ----
    const int r_base = warp_m * 64 + (lane >> 2);
    const int c_base = warp_n * 32 + ((lane & 3) << 1);
#pragma unroll
    for (int mi = 0; mi < 4; mi++) {
#pragma unroll
        for (int half = 0; half < 2; half++) {
            int l = r_base + mi * 16 + half * 8;
            if (l >= L_) continue;
            float* orow = out + ((size_t)b * L_ + l) * D_ + dtile * BN;
#pragma unroll
            for (int nj = 0; nj < 4; nj++) {
                int c = c_base + nj * 8;
                float v0 = acc[mi][nj][half * 2 + 0] + bm[c];
                float v1 = acc[mi][nj][half * 2 + 1] + bm[c + 1];
                v0 = __bfloat162float(__float2bfloat16_rn(v0));
                v1 = __bfloat162float(__float2bfloat16_rn(v1));
                *(float2*)(orow + c) = make_float2(v0, v1);
            }
        }
    }
}

// ---------------------------------------------------------------------------
extern "C" void kernel_launch(void* const* d_in, const int* in_sizes, int n_in,
                              void* d_out, int out_size) {
    const void* x_p = nullptr;
    const void* W_p = nullptr;
    const void* b_p = nullptr;
    const void* c1024[2] = {nullptr, nullptr};
    int n1024 = 0;

    for (int i = 0; i < n_in; i++) {
        switch (in_sizes[i]) {
            case 11520000: x_p = d_in[i]; break;
            case 3686400:  W_p = d_in[i]; break;
            case 4096:     b_p = d_in[i]; break;
            case 1024: if (n1024 < 2) c1024[n1024++] = d_in[i]; break;
            default: break;
        }
    }
    if (!x_p || !W_p || !b_p || n1024 != 2) {
        x_p = d_in[0]; c1024[0] = d_in[1]; c1024[1] = d_in[2];
        W_p = d_in[3]; b_p = d_in[4];
    }

    float* out = (float*)d_out;

    cudaFuncSetAttribute(moe_hmma_kernel,
                         cudaFuncAttributeMaxDynamicSharedMemorySize, SMEM_TOTAL);

    gates_kernel<<<1, B_>>>(c1024[0], c1024[1]);
    split_x_kernel<<<(NROWS * (FP / 8) + 255) / 256, 256>>>((const float*)x_p);

    dim3 grid(D_ / BN, B_);   // (4, 128)
    moe_hmma_kernel<<<grid, 256, SMEM_TOTAL>>>((const float*)W_p,
                                               (const float*)b_p, out);
}